// round 11
// baseline (speedup 1.0000x reference)
#include <cuda_runtime.h>
#include <math.h>

// Resonance synth. Phase/env cumsum emulates XLA ReduceWindowRewriter
// (base_length = 16, applied recursively; jax lowers cumsum via reduce_window):
//   level0: [2048,16] naive seq inner prefixes; S[r] = last
//   level1: [128,16] over S;  level2: [8,16] over S1;  bottom: naive seq over 8
//   scan_k = fl(inner_k + E_k(row)),  E = exclusive (pad/slice, exact)
// Final: P(16r+c) = fl(inner0(r,c) + E0(r)).
// Harness has NO fast-math (rounds 2==3 bit-identical) => sinf/expf accurate.

#define NSAMP 32768
#define NFRM  128
#define NHARM 32
#define NBE   64
#define NH    (NBE * NHARM)
#define NB0   2048
#define NB1   128
#define NB2   8

#define MIN_FREQ_F   ((float)(40.0 / 11025.0))
#define FREQ_SCALE_F ((float)(4000.0 / 11025.0 - 40.0 / 11025.0))
#define TWO_PI_F     ((float)(2.0 * 3.14159265358979323846))

// Per-sample cumsum term, exactly as the reference computes it in fp32:
// lin_interp (align_corners=False, 128 -> 32768) of constant freq, * fl32(2pi).
__device__ __forceinline__ float term_eval(int j, float freq) {
    float c = ((float)j + 0.5f) * (1.0f / 256.0f) - 0.5f;   // exact
    c = fminf(fmaxf(c, 0.0f), 127.0f);
    float fi0 = floorf(c);
    float w = c - fi0;                                       // exact
    float fs = __fadd_rn(__fmul_rn(freq, 1.0f - w), __fmul_rn(freq, w));
    return __fmul_rn(fs, TWO_PI_F);
}

__device__ __forceinline__ float harmonic_freq(const float* f0, const float* factors, int h) {
    int f  = h & (NHARM - 1);
    int be = h >> 5;
    float f0s = __fadd_rn(MIN_FREQ_F, __fmul_rn(FREQ_SCALE_F, f0[be]));
    return __fmul_rn(f0s, factors[f]);
}

__global__ __launch_bounds__(1024) void resonance_kernel(
    const float* __restrict__ f0, const float* __restrict__ res,
    const float* __restrict__ factors, float* __restrict__ out)
{
    int h  = blockIdx.x;
    int f  = h & (NHARM - 1);
    int be = h >> 5;

    float freq = harmonic_freq(f0, factors, h);
    if (freq >= 1.0f) return;        // aliased harmonic contributes exactly 0

    __shared__ float S[NB0];         // level-0 16-block sums
    __shared__ float scan0[NB0];     // inclusive outer scan of S
    __shared__ float inner1[NB1*16]; // level-1 inner prefixes over S
    __shared__ float inner2[NB2*16]; // level-2 inner prefixes over S1
    __shared__ float E2[NB2];
    __shared__ float scan1[NB1];
    __shared__ float env[NFRM];
    __shared__ float epre[16];       // env inner prefixes (constant L rows identical)
    __shared__ float eE[NB2];        // env exclusive bottom prefixes

    int t = threadIdx.x;

    // ---- level-0 block sums (thread t owns blocks 2t, 2t+1) ----
    #pragma unroll
    for (int rr = 0; rr < 2; rr++) {
        int r = 2 * t + rr;
        float a = 0.0f;
        #pragma unroll
        for (int c = 0; c < 16; c++)
            a = __fadd_rn(a, term_eval(r * 16 + c, freq));
        S[r] = a;
    }

    // ---- envelope bottom pieces (thread 0; tiny) ----
    if (t == 0) {
        float L = (float)log((double)res[be * NHARM + f] + 1e-12);
        float a = 0.0f;
        #pragma unroll
        for (int c = 0; c < 16; c++) { a = __fadd_rn(a, L); epre[c] = a; }
        float rs = epre[15];         // every env row sum is identical
        float b = 0.0f;
        eE[0] = 0.0f;
        #pragma unroll
        for (int i = 0; i < NB2 - 1; i++) { b = __fadd_rn(b, rs); eE[i + 1] = b; }
    }
    __syncthreads();

    // ---- level-1 inner prefixes over S ----
    if (t < NB1) {
        float a = 0.0f;
        #pragma unroll
        for (int c = 0; c < 16; c++) {
            a = __fadd_rn(a, S[t * 16 + c]);
            inner1[t * 16 + c] = a;
        }
    }
    // env frames: env[k] = exp(fl(epre[c] + eE[r]))
    if (t < NFRM)
        env[t] = expf(__fadd_rn(epre[t & 15], eE[t >> 4]));
    __syncthreads();

    // ---- level-2 inner prefixes over S1 (S1[x] = inner1[x*16+15]) ----
    if (t < NB2) {
        float a = 0.0f;
        #pragma unroll
        for (int c = 0; c < 16; c++) {
            a = __fadd_rn(a, inner1[(t * 16 + c) * 16 + 15]);
            inner2[t * 16 + c] = a;
        }
    }
    __syncthreads();

    // ---- bottom naive scan over S2[8] (S2[x] = inner2[x*16+15]) ----
    if (t == 0) {
        float a = 0.0f;
        E2[0] = 0.0f;
        #pragma unroll
        for (int i = 0; i < NB2 - 1; i++) {
            a = __fadd_rn(a, inner2[i * 16 + 15]);
            E2[i + 1] = a;
        }
    }
    __syncthreads();

    // ---- scan1[k1] = fl(inner2[k1] + E2[k1/16]) ----
    if (t < NB1)
        scan1[t] = __fadd_rn(inner2[t], E2[t >> 4]);
    __syncthreads();

    // ---- scan0[k] = fl(inner1[k] + E1[k/16]),  E1[r1] = scan1[r1-1] ----
    #pragma unroll
    for (int rr = 0; rr < 2; rr++) {
        int k = 2 * t + rr;
        int r1 = k >> 4;
        float E1 = r1 ? scan1[r1 - 1] : 0.0f;
        scan0[k] = __fadd_rn(inner1[k], E1);
    }
    __syncthreads();

    // ---- synthesis: P(16r+c) = fl(inner0(r,c) + E0[r]), E0[r] = scan0[r-1] ----
    float* dst = out + (size_t)be * NSAMP;
    #pragma unroll
    for (int rr = 0; rr < 2; rr++) {
        int r = 2 * t + rr;
        float E0 = r ? scan0[r - 1] : 0.0f;
        float a = 0.0f;
        #pragma unroll
        for (int c = 0; c < 16; c++) {
            int j = r * 16 + c;
            a = __fadd_rn(a, term_eval(j, freq));
            float P = __fadd_rn(a, E0);
            float sn = sinf(P);

            float cc = ((float)j + 0.5f) * (1.0f / 256.0f) - 0.5f;
            cc = fminf(fmaxf(cc, 0.0f), 127.0f);
            float fi0 = floorf(cc);
            float w = cc - fi0;
            int i0 = (int)fi0;
            int i1 = min(i0 + 1, NFRM - 1);
            float e = __fadd_rn(__fmul_rn(env[i0], 1.0f - w), __fmul_rn(env[i1], w));

            atomicAdd(dst + j, __fmul_rn(e, sn));
        }
    }
}

__global__ void zero_kernel(float4* out) {
    out[blockIdx.x * blockDim.x + threadIdx.x] = make_float4(0.f, 0.f, 0.f, 0.f);
}

extern "C" void kernel_launch(void* const* d_in, const int* in_sizes, int n_in,
                              void* d_out, int out_size) {
    const float* f0      = (const float*)d_in[0];
    const float* res     = (const float*)d_in[1];
    const float* factors = (const float*)d_in[2];
    float* out = (float*)d_out;

    zero_kernel<<<out_size / (4 * 512), 512>>>((float4*)out);
    resonance_kernel<<<NH, 1024>>>(f0, res, factors, out);
}

// round 12
// speedup vs baseline: 2.1348x; 2.1348x over previous
#include <cuda_runtime.h>
#include <math.h>

// Resonance synth. Phase/env cumsum emulates XLA ReduceWindowRewriter
// (base_length=16, recursive), bit-matching the reference (round 11 pass).
// Kernel 1: per live harmonic, compute scan0[2048] block prefixes + env[128].
// Kernel 2: per (be, 16-sample block) thread, loop live harmonics, register
//           accumulate, single coalesced store. No atomics, no zero pass.
// sin: 2-term Cody-Waite reduction mod 2pi (C1 exact) + fast-path sinf.

#define NSAMP 32768
#define NFRM  128
#define NHARM 32
#define NBE   64
#define NH    (NBE * NHARM)
#define NB0   2048
#define NB1   128
#define NB2   8

#define MIN_FREQ_F   ((float)(40.0 / 11025.0))
#define FREQ_SCALE_F ((float)(4000.0 / 11025.0 - 40.0 / 11025.0))
#define TWO_PI_F     ((float)(2.0 * 3.14159265358979323846))
#define INV_2PI_F    0.15915494309189535f
#define CW_C1        6.28125f                      // exact in 9 bits
#define CW_C2        1.9353071795864769e-3f        // fl32(2pi - C1)

__device__ float g_E0[NH * NB0];    // inclusive scan0 per harmonic (16 MB)
__device__ float g_env[NH * NFRM];  // envelope frames per harmonic (1 MB)

// term for j with j mod 256 == m, valid for 128 <= j < 32640.
// w exact: m<128 -> (2m+257)/512 ; m>=128 -> (2m-255)/512  (see derivation).
__device__ __forceinline__ float term_m(int m, float freq) {
    float w = (m < 128) ? (float)(2 * m + 257) * (1.0f / 512.0f)
                        : (float)(2 * m - 255) * (1.0f / 512.0f);
    float fs = __fadd_rn(__fmul_rn(freq, 1.0f - w), __fmul_rn(freq, w));
    return __fmul_rn(fs, TWO_PI_F);
}

__device__ __forceinline__ float harmonic_freq(const float* f0, const float* factors, int h) {
    int f  = h & (NHARM - 1);
    int be = h >> 5;
    float f0s = __fadd_rn(MIN_FREQ_F, __fmul_rn(FREQ_SCALE_F, f0[be]));
    return __fmul_rn(f0s, factors[f]);
}

// ---- Kernel 1: exact rewriter scan -> g_E0, env -> g_env ----
__global__ __launch_bounds__(128) void scan_kernel(
    const float* __restrict__ f0, const float* __restrict__ res,
    const float* __restrict__ factors)
{
    int h = blockIdx.x;
    float freq = harmonic_freq(f0, factors, h);
    if (freq >= 1.0f) return;            // aliased: synth skips it too

    __shared__ float tbl[256];
    __shared__ float S[NB0];
    __shared__ float inner2[NB1];
    __shared__ float scan1[NB1];
    __shared__ float Smod[17];           // 16 periodic block sums + edge sum
    __shared__ float E2s[NB2];
    __shared__ float epre[16];
    __shared__ float eEs[NB2];

    int t = threadIdx.x;
    float t0 = __fmul_rn(freq, TWO_PI_F);   // term for w == 0 (edges)

    for (int m = t; m < 256; m += 128) tbl[m] = term_m(m, freq);
    __syncthreads();

    // 17 distinct level-0 block sums (sequential 16-fold, exact order)
    if (t < 16) {
        float a = 0.0f;
        #pragma unroll
        for (int c = 0; c < 16; c++) a = __fadd_rn(a, tbl[t * 16 + c]);
        Smod[t] = a;
    } else if (t == 16) {
        float a = 0.0f;
        #pragma unroll
        for (int c = 0; c < 16; c++) a = __fadd_rn(a, t0);
        Smod[16] = a;
    }
    // env bottom pieces (thread 17; independent)
    if (t == 17) {
        float L = (float)log((double)res[h] + 1e-12);
        float a = 0.0f;
        #pragma unroll
        for (int c = 0; c < 16; c++) { a = __fadd_rn(a, L); epre[c] = a; }
        float rs = epre[15];
        float b = 0.0f;
        eEs[0] = 0.0f;
        #pragma unroll
        for (int i = 0; i < NB2 - 1; i++) { b = __fadd_rn(b, rs); eEs[i + 1] = b; }
    }
    __syncthreads();

    // S[2048]
    for (int k = t; k < NB0; k += 128)
        S[k] = (k < 8 || k >= 2040) ? Smod[16] : Smod[k & 15];
    // env frames out
    if (t < NFRM)
        g_env[h * NFRM + t] = expf(__fadd_rn(epre[t & 15], eEs[t >> 4]));
    __syncthreads();

    // inner1 in place: thread t owns window t (16 consecutive S)
    {
        float a = 0.0f;
        #pragma unroll
        for (int c = 0; c < 16; c++) {
            a = __fadd_rn(a, S[t * 16 + c]);
            S[t * 16 + c] = a;
        }
    }
    __syncthreads();

    // inner2 over S1[x] = S[x*16+15]
    if (t < NB2) {
        float a = 0.0f;
        #pragma unroll
        for (int c = 0; c < 16; c++) {
            a = __fadd_rn(a, S[(t * 16 + c) * 16 + 15]);
            inner2[t * 16 + c] = a;
        }
    }
    __syncthreads();

    // bottom naive exclusive scan over S2[u] = inner2[u*16+15]
    if (t == 0) {
        float a = 0.0f;
        E2s[0] = 0.0f;
        #pragma unroll
        for (int i = 0; i < NB2 - 1; i++) {
            a = __fadd_rn(a, inner2[i * 16 + 15]);
            E2s[i + 1] = a;
        }
    }
    __syncthreads();

    scan1[t] = __fadd_rn(inner2[t], E2s[t >> 4]);
    __syncthreads();

    // scan0[k] = fl(inner1[k] + E1[k/16]) -> global
    for (int k = t; k < NB0; k += 128) {
        int r1 = k >> 4;
        float E1 = r1 ? scan1[r1 - 1] : 0.0f;
        g_E0[h * NB0 + k] = __fadd_rn(S[k], E1);
    }
}

// ---- Kernel 2: synthesis. Thread = one 16-sample block of one be. ----
__global__ __launch_bounds__(256) void synth_kernel(
    const float* __restrict__ f0, const float* __restrict__ factors,
    float* __restrict__ out)
{
    int be = blockIdx.x >> 3;
    int q  = blockIdx.x & 7;
    int t  = threadIdx.x;
    int r  = q * 256 + t;            // block index 0..2047 (same for all harmonics)

    __shared__ float tbl[256];
    __shared__ float envs[NFRM];

    float acc[16];
    #pragma unroll
    for (int c = 0; c < 16; c++) acc[c] = 0.0f;

    float f0s = __fadd_rn(MIN_FREQ_F, __fmul_rn(FREQ_SCALE_F, f0[be]));
    bool edge = (r < 8 || r >= 2040);
    int mbase = (r & 15) * 16;

    for (int f = 0; f < NHARM; f++) {
        float freq = __fmul_rn(f0s, factors[f]);
        if (freq >= 1.0f) continue;           // uniform across CTA
        int h = be * NHARM + f;

        __syncthreads();
        if (t < 128) {
            tbl[t]       = term_m(t, freq);
            tbl[t + 128] = term_m(t + 128, freq);
            envs[t]      = g_env[h * NFRM + t];
        }
        __syncthreads();

        float E0 = r ? g_E0[h * NB0 + r - 1] : 0.0f;
        float t0 = __fmul_rn(freq, TWO_PI_F);
        float a = 0.0f;

        #pragma unroll
        for (int c = 0; c < 16; c++) {
            float trm = edge ? t0 : tbl[mbase + c];
            a = __fadd_rn(a, trm);
            float P = __fadd_rn(a, E0);        // reference's exact fp32 phase

            // reduce mod 2pi (C1 exact, 2-term CW; err ~2e-6 rad), fast sinf
            float k  = rintf(P * INV_2PI_F);
            float rr = fmaf(-k, CW_C1, P);
            rr = fmaf(-k, CW_C2, rr);
            float sn = sinf(rr);

            // envelope lin_interp (error budget permissive here)
            int j = r * 16 + c;
            float cc = fminf(fmaxf((float)j * (1.0f / 256.0f) + (0.5f / 256.0f) - 0.5f, 0.0f), 127.0f);
            float fi = floorf(cc);
            float w = cc - fi;
            int i0 = (int)fi;
            int i1 = min(i0 + 1, NFRM - 1);
            float e = __fadd_rn(__fmul_rn(envs[i0], 1.0f - w), __fmul_rn(envs[i1], w));

            acc[c] = __fadd_rn(acc[c], __fmul_rn(e, sn));
        }
    }

    float4* dst = (float4*)(out + (size_t)be * NSAMP + r * 16);
    #pragma unroll
    for (int v = 0; v < 4; v++)
        dst[v] = make_float4(acc[4 * v], acc[4 * v + 1], acc[4 * v + 2], acc[4 * v + 3]);
}

extern "C" void kernel_launch(void* const* d_in, const int* in_sizes, int n_in,
                              void* d_out, int out_size) {
    const float* f0      = (const float*)d_in[0];
    const float* res     = (const float*)d_in[1];
    const float* factors = (const float*)d_in[2];
    float* out = (float*)d_out;

    scan_kernel<<<NH, 128>>>(f0, res, factors);
    synth_kernel<<<NBE * 8, 256>>>(f0, factors, out);
}